// round 17
// baseline (speedup 1.0000x reference)
#include <cuda_runtime.h>

// Fixed problem shapes
#define T_STEPS 5
#define BS      32
#define C       64
#define H       64
#define W       64
#define VTH     1.0f
// gamma = DROP_RATE / BLOCK_SIZE^2 = 0.1 / 49
#define GAMMA   0.002040816326530612f

#define VEC_PER_T   2097152                   // BS*C*H*W/4

// ---------------------------------------------------------------------------
// Single fused kernel, NO cross-block dependencies (R16 + L2 prefetch).
// Block = (b, h, cg): cg in {0,1}, 32 channels x 64 w x 5 t; 512 threads,
// ONE float4 site per thread (1 u-state, 5 ld + 5 st).
// Prologue: per-t 64-bit drop bitmaps via atomicOr of dilated seed windows;
// keep float mask derived with one shift per entry. While the prologue's mr
// load + barriers are pending, prefetch.global.L2 keeps DRAM streaming on
// this thread's t=0/t=1 x lines (zero register cost).
// ---------------------------------------------------------------------------
__global__ void __launch_bounds__(512)
fused_kernel(const float4* __restrict__ x,
             const float4* __restrict__ mr4,
             float4* __restrict__ out) {
    __shared__ unsigned long long s_drop[T_STEPS];
    __shared__ __align__(16) float s_bm[T_STEPS * W];     // keep mask, all t

    const int bid = blockIdx.x;
    const int b   = bid >> 7;              // 0..31
    const int h   = (bid >> 1) & 63;       // 0..63
    const int cg  = bid & 1;               // 0..1 (32 channels each)
    const int tid = threadIdx.x;

    // body addressing (needed early for prefetch)
    const int q = tid & 15;
    const int c = (cg << 5) + (tid >> 4);                 // 0..63
    const int base = ((((b << 6) | c) << 6) | h) * 16 + q;

    // fire-and-forget L2 prefetch of the first two timesteps' lines
    asm volatile("prefetch.global.L2 [%0];" :: "l"(x + base));
    asm volatile("prefetch.global.L2 [%0];" :: "l"(x + base + VEC_PER_T));

    if (tid < T_STEPS) s_drop[tid] = 0ull;
    __syncthreads();

    // ---- gather seeds: 560 float4 (5 t x 7 rows x 16 q), 2 fixed passes ----
    #pragma unroll
    for (int j = 0; j < 2; ++j) {
        const int i = tid + j * 512;
        if (i < T_STEPS * 7 * 16) {
            const int t  = i / 112;
            const int rr = (i - t * 112) >> 4;
            const int qq = i & 15;
            const int r  = h - 3 + rr;
            if (r >= 0 && r < H) {
                const float4 v = mr4[((t * BS + b) << 10) + (r << 4) + qq];
                if (v.x < GAMMA || v.y < GAMMA || v.z < GAMMA || v.w < GAMMA) {
                    const int w0 = qq << 2;
                    unsigned long long win = 0ull;
                    #define ADD_SEED(F, DW)                                   \
                        if (F < GAMMA) {                                      \
                            const int pw = w0 + DW;                           \
                            const int lo = (pw - 3 < 0) ? 0 : pw - 3;         \
                            const int hi = (pw + 3 > 63) ? 63 : pw + 3;       \
                            win |= (((1ull << (hi - lo + 1)) - 1ull) << lo);  \
                        }
                    ADD_SEED(v.x, 0) ADD_SEED(v.y, 1) ADD_SEED(v.z, 2) ADD_SEED(v.w, 3)
                    #undef ADD_SEED
                    atomicOr(&s_drop[t], win);
                }
            }
        }
    }
    __syncthreads();

    // ---- build keep mask s_bm[t*64 + w]: one shift per entry, single pass ----
    if (tid < T_STEPS * W) {
        const int t = tid >> 6;
        const int w = tid & 63;
        s_bm[tid] = ((s_drop[t] >> w) & 1ull) ? 0.0f : 1.0f;
    }
    __syncthreads();

    // ---- LIF scan: one float4 site per thread (lean body) ----
    const float4* __restrict__ bm4s = reinterpret_cast<const float4*>(s_bm);

    float4 u = make_float4(0.f, 0.f, 0.f, 0.f);

    #pragma unroll
    for (int t = 0; t < T_STEPS; ++t) {
        const float4 xt = x[base + t * VEC_PER_T];
        const float4 bm = bm4s[(t << 4) + q];
        float4 o;

        u.x = (u.x > VTH) ? xt.x : fmaf(0.5f, u.x, xt.x);
        u.y = (u.y > VTH) ? xt.y : fmaf(0.5f, u.y, xt.y);
        u.z = (u.z > VTH) ? xt.z : fmaf(0.5f, u.z, xt.z);
        u.w = (u.w > VTH) ? xt.w : fmaf(0.5f, u.w, xt.w);

        o.x = (u.x > VTH) ? bm.x : 0.0f;
        o.y = (u.y > VTH) ? bm.y : 0.0f;
        o.z = (u.z > VTH) ? bm.z : 0.0f;
        o.w = (u.w > VTH) ? bm.w : 0.0f;

        out[base + t * VEC_PER_T] = o;
    }
}

extern "C" void kernel_launch(void* const* d_in, const int* in_sizes, int n_in,
                              void* d_out, int out_size) {
    const float4* x  = (const float4*)d_in[0];
    const float4* mr = (const float4*)d_in[1];
    float4* out      = (float4*)d_out;

    fused_kernel<<<BS * H * 2, 512>>>(x, mr, out);   // 4096 blocks
}